// round 1
// baseline (speedup 1.0000x reference)
#include <cuda_runtime.h>
#include <math.h>

#define BSZ 4
#define TLEN 4096
#define DIMV 1024
#define HDIM 64
#define NH 16
#define CHK 128
#define NCH 32
#define MROWS (BSZ*TLEN)

#define Y_ELEMS ((size_t)BSZ*TLEN*DIMV)         /* 16777216 */
#define ST_ELEMS ((size_t)BSZ*NH*HDIM*HDIM)     /* 262144   */

// ---------------- scratch (device globals: no cudaMalloc allowed) ----------------
__device__ __align__(16) float g_Q[MROWS*DIMV];
__device__ __align__(16) float g_K[MROWS*DIMV];
__device__ __align__(16) float g_V[MROWS*DIMV];
__device__ __align__(16) float g_BETA[MROWS*DIMV];
__device__ __align__(16) float g_LA[MROWS*DIMV];
__device__ __align__(16) float g_M[BSZ*NCH*NH*CHK];
__device__ __align__(16) float g_BM[BSZ*NCH*NH*CHK];
__device__ __align__(16) float g_SN[(size_t)BSZ*NH*NCH*HDIM*HDIM];  // state entering each chunk

__device__ __forceinline__ float softplusf(float x){
    return fmaxf(x, 0.f) + log1pf(expf(-fabsf(x)));
}

// ---------------------------------------------------------------------------
// Kernel 1: fused projections.  C[16384 x 5120] = X @ [Wq;Wk;Wv;Wbeta;Walpha]^T
// 128x128x16 SGEMM tiles, 256 threads, 8x8 microtiles (split 4+4 for conflict-free
// float4 smem fetch).  Epilogue applies bias + per-matrix activation and scatters
// to scratch buffers / d_out alpha region.
// ---------------------------------------------------------------------------
__global__ __launch_bounds__(256) void proj_kernel(
    const float* __restrict__ x,
    const float* __restrict__ Wq, const float* __restrict__ bq,
    const float* __restrict__ Wk, const float* __restrict__ bk,
    const float* __restrict__ Wv, const float* __restrict__ bv,
    const float* __restrict__ Wb, const float* __restrict__ bb,
    const float* __restrict__ Wa, const float* __restrict__ ba,
    float* __restrict__ out_alpha)
{
    __shared__ __align__(16) float As[16*132];
    __shared__ __align__(16) float Bs[16*132];

    const int m0   = blockIdx.x * 128;
    const int gsel = blockIdx.y;          // 0..39
    const int wsel = gsel >> 3;           // which weight matrix (1024/128 = 8 tiles each)
    const int n0   = (gsel & 7) * 128;    // feature offset inside that matrix

    const float* W; const float* bias;
    if      (wsel == 0){ W = Wq; bias = bq; }
    else if (wsel == 1){ W = Wk; bias = bk; }
    else if (wsel == 2){ W = Wv; bias = bv; }
    else if (wsel == 3){ W = Wb; bias = bb; }
    else               { W = Wa; bias = ba; }

    const int tid = threadIdx.x;
    const int tx = tid & 15, ty = tid >> 4;
    const int lr = tid >> 2, lc = tid & 3;

    float acc[8][8];
    #pragma unroll
    for (int i = 0; i < 8; i++)
        #pragma unroll
        for (int j = 0; j < 8; j++) acc[i][j] = 0.f;

    for (int k0 = 0; k0 < DIMV; k0 += 16){
        #pragma unroll
        for (int rr = 0; rr < 2; rr++){
            int row = lr + rr*64;
            float4 va = *(const float4*)(x + (size_t)(m0+row)*DIMV + k0 + lc*4);
            As[(lc*4+0)*132+row]=va.x; As[(lc*4+1)*132+row]=va.y;
            As[(lc*4+2)*132+row]=va.z; As[(lc*4+3)*132+row]=va.w;
            float4 vb = *(const float4*)(W + (size_t)(n0+row)*DIMV + k0 + lc*4);
            Bs[(lc*4+0)*132+row]=vb.x; Bs[(lc*4+1)*132+row]=vb.y;
            Bs[(lc*4+2)*132+row]=vb.z; Bs[(lc*4+3)*132+row]=vb.w;
        }
        __syncthreads();
        #pragma unroll
        for (int kk = 0; kk < 16; kk++){
            float4 a0 = *(const float4*)&As[kk*132 + ty*4];
            float4 a1 = *(const float4*)&As[kk*132 + 64 + ty*4];
            float4 b0 = *(const float4*)&Bs[kk*132 + tx*4];
            float4 b1 = *(const float4*)&Bs[kk*132 + 64 + tx*4];
            float a[8]  = {a0.x,a0.y,a0.z,a0.w, a1.x,a1.y,a1.z,a1.w};
            float bb8[8]= {b0.x,b0.y,b0.z,b0.w, b1.x,b1.y,b1.z,b1.w};
            #pragma unroll
            for (int i = 0; i < 8; i++)
                #pragma unroll
                for (int j = 0; j < 8; j++) acc[i][j] += a[i]*bb8[j];
        }
        __syncthreads();
    }

    const float scale = 0.125f;  // HDIM^-0.5
    #pragma unroll
    for (int i = 0; i < 8; i++){
        int row = (i < 4) ? ty*4+i : 64 + ty*4 + (i-4);
        size_t gm = (size_t)(m0 + row);
        #pragma unroll
        for (int j = 0; j < 8; j++){
            int col = (j < 4) ? tx*4+j : 64 + tx*4 + (j-4);
            int ln  = n0 + col;
            float v = acc[i][j] + bias[ln];
            size_t oidx = gm*DIMV + ln;
            if      (wsel == 0) g_Q[oidx]    = v*scale;
            else if (wsel == 1) g_K[oidx]    = v*scale;
            else if (wsel == 2) g_V[oidx]    = v;
            else if (wsel == 3) g_BETA[oidx] = softplusf(v);
            else {
                float z = fminf(fmaxf(v, -10.f), 10.f);
                out_alpha[oidx] = 1.f/(1.f + expf(-z));
                // log_sigmoid(z) = min(z,0) - log1p(exp(-|z|))
                g_LA[oidx] = fminf(z, 0.f) - log1pf(expf(-fabsf(z)));
            }
        }
    }
}

// ---------------------------------------------------------------------------
// Kernel 2: per-(b,n,h) chunk stats.  m[c] = cumsum_c( mean_d log_alpha ),
// bm[c] = mean_d beta.  One block per (b,n,h), 128 threads (one per c).
// ---------------------------------------------------------------------------
__global__ __launch_bounds__(128) void mstat_kernel()
{
    const int h = blockIdx.x & 15;
    const int n = (blockIdx.x >> 4) & 31;
    const int b = blockIdx.x >> 9;
    const int c = threadIdx.x;
    size_t base = ((size_t)(b*TLEN + n*CHK + c))*DIMV + h*HDIM;
    float sla = 0.f, sbe = 0.f;
    #pragma unroll
    for (int q = 0; q < 16; q++){
        float4 la4 = *(const float4*)&g_LA[base + q*4];
        float4 be4 = *(const float4*)&g_BETA[base + q*4];
        sla += la4.x + la4.y + la4.z + la4.w;
        sbe += be4.x + be4.y + be4.z + be4.w;
    }
    sla *= (1.f/64.f);
    sbe *= (1.f/64.f);

    __shared__ float sbuf[128];
    sbuf[c] = sla;
    __syncthreads();
    for (int off = 1; off < 128; off <<= 1){
        float t = (c >= off) ? sbuf[c - off] : 0.f;
        __syncthreads();
        sbuf[c] += t;
        __syncthreads();
    }
    int oidx = ((b*NCH + n)*NH + h)*CHK + c;
    g_M[oidx]  = sbuf[c];
    g_BM[oidx] = sbe;
}

// ---------------------------------------------------------------------------
// Kernel 3: sequential state scan, one block per (b,h).  Only computes the
// 64x64 carries: S_{n+1} = asum_n * S_n + K_n^T diag(bm) V_n.  Dumps the
// state ENTERING each chunk to g_SN (used by the parallel y kernel) and the
// final state to d_out.
// ---------------------------------------------------------------------------
#define SCAN_FLOATS (64*68 + 128*64 + 128*64 + 128)
#define SCAN_SMEM   (SCAN_FLOATS*4)

__global__ __launch_bounds__(256) void scan_state_kernel(float* __restrict__ state_out)
{
    extern __shared__ __align__(16) float smc[];
    float* St = smc;             // [q][v] stride 68
    float* Ks = St + 64*68;      // [c][k] stride 64
    float* Vs = Ks + 128*64;     // [c][v] stride 64
    float* bm = Vs + 128*64;     // [c]

    const int b = blockIdx.x >> 4;
    const int h = blockIdx.x & 15;
    const int tid = threadIdx.x;
    const int tx = tid & 15, ty = tid >> 4;

    for (int i = tid; i < 64*68; i += 256) St[i] = 0.f;
    __syncthreads();

    for (int n = 0; n < NCH; n++){
        // dump entering state
        size_t snbase = ((((size_t)b*NH + h)*NCH + n)) << 12;   // * 4096
        for (int i = tid; i < 4096; i += 256)
            g_SN[snbase + i] = St[(i >> 6)*68 + (i & 63)];
        // stage K,V chunk
        #pragma unroll
        for (int kq = 0; kq < 8; kq++){
            int id  = tid + kq*256;
            int row = id >> 4, c4 = id & 15;
            size_t ga = ((size_t)(b*TLEN + n*CHK + row))*DIMV + h*HDIM + c4*4;
            *(float4*)&Ks[row*64 + c4*4] = *(const float4*)&g_K[ga];
            *(float4*)&Vs[row*64 + c4*4] = *(const float4*)&g_V[ga];
        }
        if (tid < 128) bm[tid] = g_BM[((b*NCH + n)*NH + h)*CHK + tid];
        __syncthreads();

        float d[4][4];
        #pragma unroll
        for (int r = 0; r < 4; r++)
            #pragma unroll
            for (int cv = 0; cv < 4; cv++) d[r][cv] = 0.f;

        for (int cc = 0; cc < CHK; cc++){
            float bmv = bm[cc];
            float4 v4 = *(float4*)&Vs[cc*64 + tx*4];
            v4.x *= bmv; v4.y *= bmv; v4.z *= bmv; v4.w *= bmv;
            #pragma unroll
            for (int r = 0; r < 4; r++){
                float kv = Ks[cc*64 + ty*4 + r];
                d[r][0] += kv*v4.x; d[r][1] += kv*v4.y;
                d[r][2] += kv*v4.z; d[r][3] += kv*v4.w;
            }
        }
        float asum = __expf(g_M[((b*NCH + n)*NH + h)*CHK + 127]);
        #pragma unroll
        for (int r = 0; r < 4; r++)
            #pragma unroll
            for (int cv = 0; cv < 4; cv++){
                int idx = (ty*4 + r)*68 + tx*4 + cv;
                St[idx] = St[idx]*asum + d[r][cv];
            }
        __syncthreads();
    }
    size_t ob = ((size_t)(b*NH + h)) << 12;
    for (int i = tid; i < 4096; i += 256)
        state_out[ob + i] = St[(i >> 6)*68 + (i & 63)];
}

// ---------------------------------------------------------------------------
// Kernel 4: fused intra-chunk attention + inter-chunk memory readout.
// One block per (b,n,h):
//   S = (Q K^T) .* decay(m)                (128x128, K=64)
//   y = S @ (V.*beta) + curve .* (Q @ S_n) (128x64)
// written straight to d_out.
// ---------------------------------------------------------------------------
#define INTRA_FLOATS (64*132 + 64*132 + 128*132 + 128*64 + 64*68 + 128)
#define INTRA_SMEM   (INTRA_FLOATS*4)

__global__ __launch_bounds__(256) void intra_kernel(float* __restrict__ y_out)
{
    extern __shared__ __align__(16) float smi[];
    float* QT  = smi;              // [dd][i] stride 132
    float* KT  = QT + 64*132;      // [dd][j] stride 132
    float* Ssm = KT + 64*132;      // [i][j]  stride 132
    float* VB  = Ssm + 128*132;    // [j][dd] stride 64
    float* SN  = VB + 128*64;      // [q][k2] stride 68
    float* msh = SN + 64*68;       // [c]

    const int h = blockIdx.x & 15;
    const int n = (blockIdx.x >> 4) & 31;
    const int b = blockIdx.x >> 9;
    const int tid = threadIdx.x;
    const int tx = tid & 15, ty = tid >> 4;

    #pragma unroll
    for (int kq = 0; kq < 8; kq++){
        int id  = tid + kq*256;
        int row = id >> 4, c4 = id & 15;
        size_t ga = ((size_t)(b*TLEN + n*CHK + row))*DIMV + h*HDIM + c4*4;
        float4 q4  = *(const float4*)&g_Q[ga];
        float4 k4  = *(const float4*)&g_K[ga];
        float4 v4  = *(const float4*)&g_V[ga];
        float4 be4 = *(const float4*)&g_BETA[ga];
        int dd = c4*4;
        QT[(dd+0)*132+row]=q4.x; QT[(dd+1)*132+row]=q4.y;
        QT[(dd+2)*132+row]=q4.z; QT[(dd+3)*132+row]=q4.w;
        KT[(dd+0)*132+row]=k4.x; KT[(dd+1)*132+row]=k4.y;
        KT[(dd+2)*132+row]=k4.z; KT[(dd+3)*132+row]=k4.w;
        float4 vb4;
        vb4.x = v4.x*be4.x; vb4.y = v4.y*be4.y;
        vb4.z = v4.z*be4.z; vb4.w = v4.w*be4.w;
        *(float4*)&VB[row*64 + dd] = vb4;
    }
    {
        size_t snbase = ((((size_t)b*NH + h)*NCH + n)) << 12;
        for (int i = tid; i < 4096; i += 256)
            SN[(i >> 6)*68 + (i & 63)] = g_SN[snbase + i];
        if (tid < 128) msh[tid] = g_M[((b*NCH + n)*NH + h)*CHK + tid];
    }
    __syncthreads();

    // ---- GEMM1: S = Q K^T over dd=64 ----
    float acc1[8][8];
    #pragma unroll
    for (int i = 0; i < 8; i++)
        #pragma unroll
        for (int j = 0; j < 8; j++) acc1[i][j] = 0.f;

    for (int dd = 0; dd < 64; dd++){
        float4 a0 = *(float4*)&QT[dd*132 + ty*4];
        float4 a1 = *(float4*)&QT[dd*132 + 64 + ty*4];
        float4 b0 = *(float4*)&KT[dd*132 + tx*4];
        float4 b1 = *(float4*)&KT[dd*132 + 64 + tx*4];
        float a[8]  = {a0.x,a0.y,a0.z,a0.w, a1.x,a1.y,a1.z,a1.w};
        float bb8[8]= {b0.x,b0.y,b0.z,b0.w, b1.x,b1.y,b1.z,b1.w};
        #pragma unroll
        for (int i = 0; i < 8; i++)
            #pragma unroll
            for (int j = 0; j < 8; j++) acc1[i][j] += a[i]*bb8[j];
    }

    // ---- decay mask + store S ----
    #pragma unroll
    for (int i = 0; i < 8; i++){
        int ig = (i < 4) ? ty*4+i : 64 + ty*4 + (i-4);
        float mi = msh[ig];
        #pragma unroll
        for (int j = 0; j < 8; j++){
            int jg = (j < 4) ? tx*4+j : 64 + tx*4 + (j-4);
            float s = (jg <= ig) ? acc1[i][j]*__expf(mi - msh[jg]) : 0.f;
            Ssm[ig*132 + jg] = s;
        }
    }
    __syncthreads();

    // ---- GEMM2: y_intra = S @ VB   and   GEMM3: mem = Q @ SN ----
    float accY[8][4], accM[8][4];
    #pragma unroll
    for (int i = 0; i < 8; i++)
        #pragma unroll
        for (int c = 0; c < 4; c++){ accY[i][c] = 0.f; accM[i][c] = 0.f; }

    for (int j = 0; j < 128; j++){
        float4 vb4 = *(float4*)&VB[j*64 + tx*4];
        #pragma unroll
        for (int i = 0; i < 8; i++){
            int ig = (i < 4) ? ty*4+i : 64 + ty*4 + (i-4);
            float s = Ssm[ig*132 + j];
            accY[i][0] += s*vb4.x; accY[i][1] += s*vb4.y;
            accY[i][2] += s*vb4.z; accY[i][3] += s*vb4.w;
        }
    }
    for (int q = 0; q < 64; q++){
        float4 s4 = *(float4*)&SN[q*68 + tx*4];
        #pragma unroll
        for (int i = 0; i < 8; i++){
            int ig = (i < 4) ? ty*4+i : 64 + ty*4 + (i-4);
            float qv = QT[q*132 + ig];
            accM[i][0] += qv*s4.x; accM[i][1] += qv*s4.y;
            accM[i][2] += qv*s4.z; accM[i][3] += qv*s4.w;
        }
    }

    #pragma unroll
    for (int i = 0; i < 8; i++){
        int ig = (i < 4) ? ty*4+i : 64 + ty*4 + (i-4);
        float cv = __expf(msh[ig]);
        float4 o;
        o.x = accY[i][0] + cv*accM[i][0];
        o.y = accY[i][1] + cv*accM[i][1];
        o.z = accY[i][2] + cv*accM[i][2];
        o.w = accY[i][3] + cv*accM[i][3];
        size_t oa = ((size_t)(b*TLEN + n*CHK + ig))*DIMV + h*HDIM + tx*4;
        *(float4*)&y_out[oa] = o;
    }
}

// ---------------------------------------------------------------------------
extern "C" void kernel_launch(void* const* d_in, const int* in_sizes, int n_in,
                              void* d_out, int out_size)
{
    const float* x  = (const float*)d_in[0];
    const float* Wq = (const float*)d_in[1];
    const float* bq = (const float*)d_in[2];
    const float* Wk = (const float*)d_in[3];
    const float* bk = (const float*)d_in[4];
    const float* Wv = (const float*)d_in[5];
    const float* bv = (const float*)d_in[6];
    const float* Wb = (const float*)d_in[7];
    const float* bb = (const float*)d_in[8];
    const float* Wa = (const float*)d_in[9];
    const float* ba = (const float*)d_in[10];

    float* out       = (float*)d_out;
    float* y_out     = out;                       // (B,T,DIM)
    float* state_out = out + Y_ELEMS;             // (B,H,d,d)
    float* alpha_out = out + Y_ELEMS + ST_ELEMS;  // (B,T,H,d)

    cudaFuncSetAttribute(scan_state_kernel,
                         cudaFuncAttributeMaxDynamicSharedMemorySize, SCAN_SMEM);
    cudaFuncSetAttribute(intra_kernel,
                         cudaFuncAttributeMaxDynamicSharedMemorySize, INTRA_SMEM);

    dim3 gp(128, 40);
    proj_kernel<<<gp, 256>>>(x, Wq, bq, Wk, bk, Wv, bv, Wb, bb, Wa, ba, alpha_out);
    mstat_kernel<<<BSZ*NCH*NH, 128>>>();
    scan_state_kernel<<<BSZ*NH, 256, SCAN_SMEM>>>(state_out);
    intra_kernel<<<BSZ*NCH*NH, 256, INTRA_SMEM>>>(y_out);
}

// round 4
// speedup vs baseline: 1.0969x; 1.0969x over previous
#include <cuda_runtime.h>
#include <cuda_bf16.h>
#include <math.h>
#include <stdint.h>

#define BSZ 4
#define TLEN 4096
#define DIMV 1024
#define HDIM 64
#define NH 16
#define CHK 128
#define NCH 32
#define MROWS (BSZ*TLEN)
#define NTOT 5120               /* 5 weight matrices concatenated */

#define Y_ELEMS ((size_t)BSZ*TLEN*DIMV)         /* 16777216 */
#define ST_ELEMS ((size_t)BSZ*NH*HDIM*HDIM)     /* 262144   */

// ---------------- scratch (device globals: no cudaMalloc allowed) ----------------
__device__ __align__(16) float g_Q[MROWS*DIMV];
__device__ __align__(16) float g_K[MROWS*DIMV];
__device__ __align__(16) float g_V[MROWS*DIMV];
__device__ __align__(16) float g_BETA[MROWS*DIMV];
__device__ __align__(16) float g_LA[MROWS*DIMV];
__device__ __align__(16) float g_M[BSZ*NCH*NH*CHK];
__device__ __align__(16) float g_BM[BSZ*NCH*NH*CHK];
__device__ __align__(16) float g_SN[(size_t)BSZ*NH*NCH*HDIM*HDIM];

// bf16 hi/lo splits for tensor-core projection
__device__ __align__(16) __nv_bfloat16 g_XH[(size_t)MROWS*DIMV];
__device__ __align__(16) __nv_bfloat16 g_XL[(size_t)MROWS*DIMV];
__device__ __align__(16) __nv_bfloat16 g_WH[(size_t)NTOT*DIMV];
__device__ __align__(16) __nv_bfloat16 g_WL[(size_t)NTOT*DIMV];

__device__ __forceinline__ float softplusf(float x){
    return fmaxf(x, 0.f) + log1pf(expf(-fabsf(x)));
}

__device__ __forceinline__ uint32_t smem_to_u32(const void* p){
    uint32_t a;
    asm("{ .reg .u64 t; cvta.to.shared.u64 t, %1; cvt.u32.u64 %0, t; }" : "=r"(a) : "l"(p));
    return a;
}

#define CPASYNC(dst_u32, src_ptr) \
    asm volatile("cp.async.cg.shared.global [%0], [%1], 16;" :: "r"(dst_u32), "l"(src_ptr))
#define CP_COMMIT  asm volatile("cp.async.commit_group;" ::: "memory")
#define CP_WAIT1   asm volatile("cp.async.wait_group 1;" ::: "memory")
#define CP_WAIT0   asm volatile("cp.async.wait_group 0;" ::: "memory")

#define MMA_BF16(d, a0,a1,a2,a3, b0,b1) \
    asm volatile("mma.sync.aligned.m16n8k16.row.col.f32.bf16.bf16.f32 " \
        "{%0,%1,%2,%3},{%4,%5,%6,%7},{%8,%9},{%0,%1,%2,%3};" \
        : "+f"((d)[0]), "+f"((d)[1]), "+f"((d)[2]), "+f"((d)[3]) \
        : "r"(a0), "r"(a1), "r"(a2), "r"(a3), "r"(b0), "r"(b1))

// ---------------------------------------------------------------------------
// Convert kernels: fp32 -> bf16 hi/lo splits
// ---------------------------------------------------------------------------
__global__ __launch_bounds__(256) void convert_x_kernel(const float* __restrict__ x)
{
    size_t i = ((size_t)blockIdx.x*256 + threadIdx.x)*4;
    float4 v = *(const float4*)(x + i);
    ushort4 hi, lo;
    float f; __nv_bfloat16 h;
    h = __float2bfloat16_rn(v.x); f = v.x - __bfloat162float(h); hi.x = *(unsigned short*)&h; h = __float2bfloat16_rn(f); lo.x = *(unsigned short*)&h;
    h = __float2bfloat16_rn(v.y); f = v.y - __bfloat162float(h); hi.y = *(unsigned short*)&h; h = __float2bfloat16_rn(f); lo.y = *(unsigned short*)&h;
    h = __float2bfloat16_rn(v.z); f = v.z - __bfloat162float(h); hi.z = *(unsigned short*)&h; h = __float2bfloat16_rn(f); lo.z = *(unsigned short*)&h;
    h = __float2bfloat16_rn(v.w); f = v.w - __bfloat162float(h); hi.w = *(unsigned short*)&h; h = __float2bfloat16_rn(f); lo.w = *(unsigned short*)&h;
    *(ushort4*)((unsigned short*)g_XH + i) = hi;
    *(ushort4*)((unsigned short*)g_XL + i) = lo;
}

__global__ __launch_bounds__(256) void convert_w_kernel(
    const float* __restrict__ Wq, const float* __restrict__ Wk,
    const float* __restrict__ Wv, const float* __restrict__ Wb,
    const float* __restrict__ Wa)
{
    size_t i = ((size_t)blockIdx.x*256 + threadIdx.x)*4;
    int row = (int)(i >> 10);
    int wsel = row >> 10;
    const float* W;
    if      (wsel == 0) W = Wq;
    else if (wsel == 1) W = Wk;
    else if (wsel == 2) W = Wv;
    else if (wsel == 3) W = Wb;
    else                W = Wa;
    size_t li = i - ((size_t)wsel << 20);
    float4 v = *(const float4*)(W + li);
    ushort4 hi, lo;
    float f; __nv_bfloat16 h;
    h = __float2bfloat16_rn(v.x); f = v.x - __bfloat162float(h); hi.x = *(unsigned short*)&h; h = __float2bfloat16_rn(f); lo.x = *(unsigned short*)&h;
    h = __float2bfloat16_rn(v.y); f = v.y - __bfloat162float(h); hi.y = *(unsigned short*)&h; h = __float2bfloat16_rn(f); lo.y = *(unsigned short*)&h;
    h = __float2bfloat16_rn(v.z); f = v.z - __bfloat162float(h); hi.z = *(unsigned short*)&h; h = __float2bfloat16_rn(f); lo.z = *(unsigned short*)&h;
    h = __float2bfloat16_rn(v.w); f = v.w - __bfloat162float(h); hi.w = *(unsigned short*)&h; h = __float2bfloat16_rn(f); lo.w = *(unsigned short*)&h;
    *(ushort4*)((unsigned short*)g_WH + i) = hi;
    *(ushort4*)((unsigned short*)g_WL + i) = lo;
}

// ---------------------------------------------------------------------------
// mma.sync projection GEMM: C[16384 x 5120] = X @ Wcat^T, compensated bf16.
// Block tile 128x256, warp tile 64x64, K staged 32, cp.async double buffer.
// smem row stride = 40 bf16 (80B) -> conflict-free fragment loads.
// ---------------------------------------------------------------------------
#define KTILE 32
#define NSTG 32                       /* 1024/32 */
#define SA_HI 0
#define SA_LO 10240                   /* 128*40*2 */
#define SB_HI 20480
#define SB_LO 40960                   /* 256*40*2 */
#define STAGE 61440
#define SMEM_PROJ (2*STAGE)

__global__ __launch_bounds__(256, 1) void proj_mma_kernel(
    const float* __restrict__ bq, const float* __restrict__ bk,
    const float* __restrict__ bv, const float* __restrict__ bb,
    const float* __restrict__ ba,
    float* __restrict__ out_alpha)
{
    extern __shared__ __align__(16) char smc[];
    const uint32_t sbase = smem_to_u32(smc);

    const int tid  = threadIdx.x;
    const int wid  = tid >> 5;
    const int lane = tid & 31;
    const int wm   = wid & 1;          // 2 warps in M
    const int wn   = wid >> 1;         // 4 warps in N

    const int m0   = blockIdx.x * 128;
    const int n0g  = blockIdx.y * 256;
    const int wsel = blockIdx.y >> 2;
    const int ln0  = (blockIdx.y & 3) * 256;

    const float* bias;
    if      (wsel == 0) bias = bq;
    else if (wsel == 1) bias = bk;
    else if (wsel == 2) bias = bv;
    else if (wsel == 3) bias = bb;
    else                bias = ba;

    float acc[4][8][4];
    #pragma unroll
    for (int i = 0; i < 4; i++)
        #pragma unroll
        for (int j = 0; j < 8; j++)
            #pragma unroll
            for (int c = 0; c < 4; c++) acc[i][j][c] = 0.f;

    // --------- stage loader (cp.async) ---------
    auto load_stage = [&](int buf, int k0){
        const uint32_t st = sbase + buf*STAGE;
        #pragma unroll
        for (int t = 0; t < 2; t++){
            int i = tid + t*256;             // 0..511
            int row = i >> 2, c = i & 3;
            uint32_t doff = (uint32_t)(row*80 + c*16);
            CPASYNC(st + SA_HI + doff, (const char*)(g_XH + (size_t)(m0+row)*DIMV + k0) + c*16);
            CPASYNC(st + SA_LO + doff, (const char*)(g_XL + (size_t)(m0+row)*DIMV + k0) + c*16);
        }
        #pragma unroll
        for (int t = 0; t < 4; t++){
            int i = tid + t*256;             // 0..1023
            int row = i >> 2, c = i & 3;
            uint32_t doff = (uint32_t)(row*80 + c*16);
            CPASYNC(st + SB_HI + doff, (const char*)(g_WH + (size_t)(n0g+row)*DIMV + k0) + c*16);
            CPASYNC(st + SB_LO + doff, (const char*)(g_WL + (size_t)(n0g+row)*DIMV + k0) + c*16);
        }
    };

    load_stage(0, 0);
    CP_COMMIT;

    for (int kc = 0; kc < NSTG; kc++){
        if (kc + 1 < NSTG){
            load_stage((kc + 1) & 1, (kc + 1) * KTILE);
            CP_COMMIT;
            CP_WAIT1;
        } else {
            CP_WAIT0;
        }
        __syncthreads();

        const char* sa_hi = smc + (kc & 1)*STAGE + SA_HI;
        const char* sa_lo = smc + (kc & 1)*STAGE + SA_LO;
        const char* sb_hi = smc + (kc & 1)*STAGE + SB_HI;
        const char* sb_lo = smc + (kc & 1)*STAGE + SB_LO;

        #pragma unroll
        for (int ks = 0; ks < 2; ks++){
            const uint32_t c0 = ks*32 + ((lane & 3) << 2);   // byte offset of bf16 pair
            uint32_t ah[4][4], al[4][4];
            #pragma unroll
            for (int fm = 0; fm < 4; fm++){
                int r = wm*64 + fm*16 + (lane >> 2);
                ah[fm][0] = *(const uint32_t*)(sa_hi + r*80 + c0);
                ah[fm][1] = *(const uint32_t*)(sa_hi + (r+8)*80 + c0);
                ah[fm][2] = *(const uint32_t*)(sa_hi + r*80 + c0 + 16);
                ah[fm][3] = *(const uint32_t*)(sa_hi + (r+8)*80 + c0 + 16);
                al[fm][0] = *(const uint32_t*)(sa_lo + r*80 + c0);
                al[fm][1] = *(const uint32_t*)(sa_lo + (r+8)*80 + c0);
                al[fm][2] = *(const uint32_t*)(sa_lo + r*80 + c0 + 16);
                al[fm][3] = *(const uint32_t*)(sa_lo + (r+8)*80 + c0 + 16);
            }
            #pragma unroll
            for (int fn = 0; fn < 8; fn++){
                int n = wn*64 + fn*8 + (lane >> 2);
                uint32_t bh0 = *(const uint32_t*)(sb_hi + n*80 + c0);
                uint32_t bh1 = *(const uint32_t*)(sb_hi + n*80 + c0 + 16);
                uint32_t bl0 = *(const uint32_t*)(sb_lo + n*80 + c0);
                uint32_t bl1 = *(const uint32_t*)(sb_lo + n*80 + c0 + 16);
                #pragma unroll
                for (int fm = 0; fm < 4; fm++){
                    MMA_BF16(acc[fm][fn], ah[fm][0], ah[fm][1], ah[fm][2], ah[fm][3], bh0, bh1);
                    MMA_BF16(acc[fm][fn], ah[fm][0], ah[fm][1], ah[fm][2], ah[fm][3], bl0, bl1);
                    MMA_BF16(acc[fm][fn], al[fm][0], al[fm][1], al[fm][2], al[fm][3], bh0, bh1);
                }
            }
        }
        __syncthreads();
    }

    // --------- epilogue: bias + activation, direct 8B stores ---------
    const float scale = 0.125f;
    #pragma unroll
    for (int fm = 0; fm < 4; fm++){
        int r0 = m0 + wm*64 + fm*16 + (lane >> 2);
        #pragma unroll
        for (int fn = 0; fn < 8; fn++){
            int ln = ln0 + wn*64 + fn*8 + ((lane & 3) << 1);
            float b0 = bias[ln], b1 = bias[ln+1];
            #pragma unroll
            for (int half = 0; half < 2; half++){
                int r = r0 + half*8;
                float v0 = acc[fm][fn][half*2 + 0] + b0;
                float v1 = acc[fm][fn][half*2 + 1] + b1;
                size_t oidx = (size_t)r*DIMV + ln;
                if (wsel == 0){
                    float2 o = {v0*scale, v1*scale};
                    *(float2*)&g_Q[oidx] = o;
                } else if (wsel == 1){
                    float2 o = {v0*scale, v1*scale};
                    *(float2*)&g_K[oidx] = o;
                } else if (wsel == 2){
                    float2 o = {v0, v1};
                    *(float2*)&g_V[oidx] = o;
                } else if (wsel == 3){
                    float2 o = {softplusf(v0), softplusf(v1)};
                    *(float2*)&g_BETA[oidx] = o;
                } else {
                    float z0 = fminf(fmaxf(v0,-10.f),10.f);
                    float z1 = fminf(fmaxf(v1,-10.f),10.f);
                    float2 oa = {1.f/(1.f+expf(-z0)), 1.f/(1.f+expf(-z1))};
                    *(float2*)&out_alpha[oidx] = oa;
                    float2 ol = {fminf(z0,0.f) - log1pf(expf(-fabsf(z0))),
                                 fminf(z1,0.f) - log1pf(expf(-fabsf(z1)))};
                    *(float2*)&g_LA[oidx] = ol;
                }
            }
        }
    }
}

// ---------------------------------------------------------------------------
// Kernel 2: per-(b,n,h) chunk stats
// ---------------------------------------------------------------------------
__global__ __launch_bounds__(128) void mstat_kernel()
{
    const int h = blockIdx.x & 15;
    const int n = (blockIdx.x >> 4) & 31;
    const int b = blockIdx.x >> 9;
    const int c = threadIdx.x;
    size_t base = ((size_t)(b*TLEN + n*CHK + c))*DIMV + h*HDIM;
    float sla = 0.f, sbe = 0.f;
    #pragma unroll
    for (int q = 0; q < 16; q++){
        float4 la4 = *(const float4*)&g_LA[base + q*4];
        float4 be4 = *(const float4*)&g_BETA[base + q*4];
        sla += la4.x + la4.y + la4.z + la4.w;
        sbe += be4.x + be4.y + be4.z + be4.w;
    }
    sla *= (1.f/64.f);
    sbe *= (1.f/64.f);

    __shared__ float sbuf[128];
    sbuf[c] = sla;
    __syncthreads();
    for (int off = 1; off < 128; off <<= 1){
        float t = (c >= off) ? sbuf[c - off] : 0.f;
        __syncthreads();
        sbuf[c] += t;
        __syncthreads();
    }
    int oidx = ((b*NCH + n)*NH + h)*CHK + c;
    g_M[oidx]  = sbuf[c];
    g_BM[oidx] = sbe;
}

// ---------------------------------------------------------------------------
// Kernel 3: sequential state scan, one block per (b,h)
// ---------------------------------------------------------------------------
#define SCAN_FLOATS (64*68 + 128*64 + 128*64 + 128)
#define SCAN_SMEM   (SCAN_FLOATS*4)

__global__ __launch_bounds__(256) void scan_state_kernel(float* __restrict__ state_out)
{
    extern __shared__ __align__(16) float smcx[];
    float* St = smcx;
    float* Ks = St + 64*68;
    float* Vs = Ks + 128*64;
    float* bm = Vs + 128*64;

    const int b = blockIdx.x >> 4;
    const int h = blockIdx.x & 15;
    const int tid = threadIdx.x;
    const int tx = tid & 15, ty = tid >> 4;

    for (int i = tid; i < 64*68; i += 256) St[i] = 0.f;
    __syncthreads();

    for (int n = 0; n < NCH; n++){
        size_t snbase = ((((size_t)b*NH + h)*NCH + n)) << 12;
        for (int i = tid; i < 4096; i += 256)
            g_SN[snbase + i] = St[(i >> 6)*68 + (i & 63)];
        #pragma unroll
        for (int kq = 0; kq < 8; kq++){
            int id  = tid + kq*256;
            int row = id >> 4, c4 = id & 15;
            size_t ga = ((size_t)(b*TLEN + n*CHK + row))*DIMV + h*HDIM + c4*4;
            *(float4*)&Ks[row*64 + c4*4] = *(const float4*)&g_K[ga];
            *(float4*)&Vs[row*64 + c4*4] = *(const float4*)&g_V[ga];
        }
        if (tid < 128) bm[tid] = g_BM[((b*NCH + n)*NH + h)*CHK + tid];
        __syncthreads();

        float d[4][4];
        #pragma unroll
        for (int r = 0; r < 4; r++)
            #pragma unroll
            for (int cv = 0; cv < 4; cv++) d[r][cv] = 0.f;

        for (int cc = 0; cc < CHK; cc++){
            float bmv = bm[cc];
            float4 v4 = *(float4*)&Vs[cc*64 + tx*4];
            v4.x *= bmv; v4.y *= bmv; v4.z *= bmv; v4.w *= bmv;
            #pragma unroll
            for (int r = 0; r < 4; r++){
                float kv = Ks[cc*64 + ty*4 + r];
                d[r][0] += kv*v4.x; d[r][1] += kv*v4.y;
                d[r][2] += kv*v4.z; d[r][3] += kv*v4.w;
            }
        }
        float asum = __expf(g_M[((b*NCH + n)*NH + h)*CHK + 127]);
        #pragma unroll
        for (int r = 0; r < 4; r++)
            #pragma unroll
            for (int cv = 0; cv < 4; cv++){
                int idx = (ty*4 + r)*68 + tx*4 + cv;
                St[idx] = St[idx]*asum + d[r][cv];
            }
        __syncthreads();
    }
    size_t ob = ((size_t)(b*NH + h)) << 12;
    for (int i = tid; i < 4096; i += 256)
        state_out[ob + i] = St[(i >> 6)*68 + (i & 63)];
}

// ---------------------------------------------------------------------------
// Kernel 4: fused intra-chunk attention + inter-chunk memory readout
// ---------------------------------------------------------------------------
#define INTRA_FLOATS (64*132 + 64*132 + 128*132 + 128*64 + 64*68 + 128)
#define INTRA_SMEM   (INTRA_FLOATS*4)

__global__ __launch_bounds__(256) void intra_kernel(float* __restrict__ y_out)
{
    extern __shared__ __align__(16) float smi[];
    float* QT   = smi;
    float* KTs  = QT + 64*132;
    float* Ssm  = KTs + 64*132;
    float* VB   = Ssm + 128*132;
    float* SN   = VB + 128*64;
    float* msh  = SN + 64*68;

    const int h = blockIdx.x & 15;
    const int n = (blockIdx.x >> 4) & 31;
    const int b = blockIdx.x >> 9;
    const int tid = threadIdx.x;
    const int tx = tid & 15, ty = tid >> 4;

    #pragma unroll
    for (int kq = 0; kq < 8; kq++){
        int id  = tid + kq*256;
        int row = id >> 4, c4 = id & 15;
        size_t ga = ((size_t)(b*TLEN + n*CHK + row))*DIMV + h*HDIM + c4*4;
        float4 q4  = *(const float4*)&g_Q[ga];
        float4 k4  = *(const float4*)&g_K[ga];
        float4 v4  = *(const float4*)&g_V[ga];
        float4 be4 = *(const float4*)&g_BETA[ga];
        int dd = c4*4;
        QT[(dd+0)*132+row]=q4.x; QT[(dd+1)*132+row]=q4.y;
        QT[(dd+2)*132+row]=q4.z; QT[(dd+3)*132+row]=q4.w;
        KTs[(dd+0)*132+row]=k4.x; KTs[(dd+1)*132+row]=k4.y;
        KTs[(dd+2)*132+row]=k4.z; KTs[(dd+3)*132+row]=k4.w;
        float4 vb4;
        vb4.x = v4.x*be4.x; vb4.y = v4.y*be4.y;
        vb4.z = v4.z*be4.z; vb4.w = v4.w*be4.w;
        *(float4*)&VB[row*64 + dd] = vb4;
    }
    {
        size_t snbase = ((((size_t)b*NH + h)*NCH + n)) << 12;
        for (int i = tid; i < 4096; i += 256)
            SN[(i >> 6)*68 + (i & 63)] = g_SN[snbase + i];
        if (tid < 128) msh[tid] = g_M[((b*NCH + n)*NH + h)*CHK + tid];
    }
    __syncthreads();

    float acc1[8][8];
    #pragma unroll
    for (int i = 0; i < 8; i++)
        #pragma unroll
        for (int j = 0; j < 8; j++) acc1[i][j] = 0.f;

    for (int dd = 0; dd < 64; dd++){
        float4 a0 = *(float4*)&QT[dd*132 + ty*4];
        float4 a1 = *(float4*)&QT[dd*132 + 64 + ty*4];
        float4 b0 = *(float4*)&KTs[dd*132 + tx*4];
        float4 b1 = *(float4*)&KTs[dd*132 + 64 + tx*4];
        float a[8]  = {a0.x,a0.y,a0.z,a0.w, a1.x,a1.y,a1.z,a1.w};
        float bb8[8]= {b0.x,b0.y,b0.z,b0.w, b1.x,b1.y,b1.z,b1.w};
        #pragma unroll
        for (int i = 0; i < 8; i++)
            #pragma unroll
            for (int j = 0; j < 8; j++) acc1[i][j] += a[i]*bb8[j];
    }

    #pragma unroll
    for (int i = 0; i < 8; i++){
        int ig = (i < 4) ? ty*4+i : 64 + ty*4 + (i-4);
        float mi = msh[ig];
        #pragma unroll
        for (int j = 0; j < 8; j++){
            int jg = (j < 4) ? tx*4+j : 64 + tx*4 + (j-4);
            float s = (jg <= ig) ? acc1[i][j]*__expf(mi - msh[jg]) : 0.f;
            Ssm[ig*132 + jg] = s;
        }
    }
    __syncthreads();

    float accY[8][4], accM[8][4];
    #pragma unroll
    for (int i = 0; i < 8; i++)
        #pragma unroll
        for (int c = 0; c < 4; c++){ accY[i][c] = 0.f; accM[i][c] = 0.f; }

    for (int j = 0; j < 128; j++){
        float4 vb4 = *(float4*)&VB[j*64 + tx*4];
        #pragma unroll
        for (int i = 0; i < 8; i++){
            int ig = (i < 4) ? ty*4+i : 64 + ty*4 + (i-4);
            float s = Ssm[ig*132 + j];
            accY[i][0] += s*vb4.x; accY[i][1] += s*vb4.y;
            accY[i][2] += s*vb4.z; accY[i][3] += s*vb4.w;
        }
    }
    for (int q = 0; q < 64; q++){
        float4 s4 = *(float4*)&SN[q*68 + tx*4];
        #pragma unroll
        for (int i = 0; i < 8; i++){
            int ig = (i < 4) ? ty*4+i : 64 + ty*4 + (i-4);
            float qv = QT[q*132 + ig];
            accM[i][0] += qv*s4.x; accM[i][1] += qv*s4.y;
            accM[i][2] += qv*s4.z; accM[i][3] += qv*s4.w;
        }
    }

    #pragma unroll
    for (int i = 0; i < 8; i++){
        int ig = (i < 4) ? ty*4+i : 64 + ty*4 + (i-4);
        float cv = __expf(msh[ig]);
        float4 o;
        o.x = accY[i][0] + cv*accM[i][0];
        o.y = accY[i][1] + cv*accM[i][1];
        o.z = accY[i][2] + cv*accM[i][2];
        o.w = accY[i][3] + cv*accM[i][3];
        size_t oa = ((size_t)(b*TLEN + n*CHK + ig))*DIMV + h*HDIM + tx*4;
        *(float4*)&y_out[oa] = o;
    }
}

// ---------------------------------------------------------------------------
extern "C" void kernel_launch(void* const* d_in, const int* in_sizes, int n_in,
                              void* d_out, int out_size)
{
    const float* x  = (const float*)d_in[0];
    const float* Wq = (const float*)d_in[1];
    const float* bq = (const float*)d_in[2];
    const float* Wk = (const float*)d_in[3];
    const float* bk = (const float*)d_in[4];
    const float* Wv = (const float*)d_in[5];
    const float* bv = (const float*)d_in[6];
    const float* Wb = (const float*)d_in[7];
    const float* bb = (const float*)d_in[8];
    const float* Wa = (const float*)d_in[9];
    const float* ba = (const float*)d_in[10];

    float* out       = (float*)d_out;
    float* y_out     = out;
    float* state_out = out + Y_ELEMS;
    float* alpha_out = out + Y_ELEMS + ST_ELEMS;

    cudaFuncSetAttribute(proj_mma_kernel,
                         cudaFuncAttributeMaxDynamicSharedMemorySize, SMEM_PROJ);
    cudaFuncSetAttribute(scan_state_kernel,
                         cudaFuncAttributeMaxDynamicSharedMemorySize, SCAN_SMEM);
    cudaFuncSetAttribute(intra_kernel,
                         cudaFuncAttributeMaxDynamicSharedMemorySize, INTRA_SMEM);

    convert_x_kernel<<<MROWS*DIMV/4/256, 256>>>(x);
    convert_w_kernel<<<NTOT*DIMV/4/256, 256>>>(Wq, Wk, Wv, Wb, Wa);

    dim3 gp(128, 20);
    proj_mma_kernel<<<gp, 256, SMEM_PROJ>>>(bq, bk, bv, bb, ba, alpha_out);

    mstat_kernel<<<BSZ*NCH*NH, 128>>>();
    scan_state_kernel<<<BSZ*NH, 256, SCAN_SMEM>>>(state_out);
    intra_kernel<<<BSZ*NCH*NH, 256, INTRA_SMEM>>>(y_out);
}

// round 5
// speedup vs baseline: 1.8851x; 1.7186x over previous
#include <cuda_runtime.h>
#include <cuda_bf16.h>
#include <math.h>
#include <stdint.h>

#define BSZ 4
#define TLEN 4096
#define DIMV 1024
#define HDIM 64
#define NH 16
#define CHK 128
#define NCH 32
#define MROWS (BSZ*TLEN)
#define NTOT 5120               /* 5 weight matrices concatenated */

#define Y_ELEMS ((size_t)BSZ*TLEN*DIMV)         /* 16777216 */
#define ST_ELEMS ((size_t)BSZ*NH*HDIM*HDIM)     /* 262144   */

// ---------------- scratch (device globals: no cudaMalloc allowed) ----------------
__device__ __align__(16) float g_Q[MROWS*DIMV];
__device__ __align__(16) float g_K[MROWS*DIMV];
__device__ __align__(16) float g_V[MROWS*DIMV];
__device__ __align__(16) float g_BETA[MROWS*DIMV];
__device__ __align__(16) float g_LA[MROWS*DIMV];
__device__ __align__(16) float g_M[BSZ*NCH*NH*CHK];
__device__ __align__(16) float g_BM[BSZ*NCH*NH*CHK];
__device__ __align__(16) float g_SN[(size_t)BSZ*NH*NCH*HDIM*HDIM];

// bf16 hi/lo splits for tensor-core projection
__device__ __align__(16) __nv_bfloat16 g_XH[(size_t)MROWS*DIMV];
__device__ __align__(16) __nv_bfloat16 g_XL[(size_t)MROWS*DIMV];
__device__ __align__(16) __nv_bfloat16 g_WH[(size_t)NTOT*DIMV];
__device__ __align__(16) __nv_bfloat16 g_WL[(size_t)NTOT*DIMV];

__device__ __forceinline__ float softplusf(float x){
    return fmaxf(x, 0.f) + log1pf(expf(-fabsf(x)));
}

__device__ __forceinline__ uint32_t smem_to_u32(const void* p){
    uint32_t a;
    asm("{ .reg .u64 t; cvta.to.shared.u64 t, %1; cvt.u32.u64 %0, t; }" : "=r"(a) : "l"(p));
    return a;
}

#define CPASYNC(dst_u32, src_ptr) \
    asm volatile("cp.async.cg.shared.global [%0], [%1], 16;" :: "r"(dst_u32), "l"(src_ptr))
#define CP_COMMIT  asm volatile("cp.async.commit_group;" ::: "memory")
#define CP_WAIT1   asm volatile("cp.async.wait_group 1;" ::: "memory")
#define CP_WAIT0   asm volatile("cp.async.wait_group 0;" ::: "memory")

#define MMA_BF16(d, a0,a1,a2,a3, b0,b1) \
    asm volatile("mma.sync.aligned.m16n8k16.row.col.f32.bf16.bf16.f32 " \
        "{%0,%1,%2,%3},{%4,%5,%6,%7},{%8,%9},{%0,%1,%2,%3};" \
        : "+f"((d)[0]), "+f"((d)[1]), "+f"((d)[2]), "+f"((d)[3]) \
        : "r"(a0), "r"(a1), "r"(a2), "r"(a3), "r"(b0), "r"(b1))

// ---------------------------------------------------------------------------
// Convert kernels: fp32 -> bf16 hi/lo splits
// ---------------------------------------------------------------------------
__global__ __launch_bounds__(256) void convert_x_kernel(const float* __restrict__ x)
{
    size_t i = ((size_t)blockIdx.x*256 + threadIdx.x)*4;
    float4 v = *(const float4*)(x + i);
    ushort4 hi, lo;
    float f; __nv_bfloat16 h;
    h = __float2bfloat16_rn(v.x); f = v.x - __bfloat162float(h); hi.x = *(unsigned short*)&h; h = __float2bfloat16_rn(f); lo.x = *(unsigned short*)&h;
    h = __float2bfloat16_rn(v.y); f = v.y - __bfloat162float(h); hi.y = *(unsigned short*)&h; h = __float2bfloat16_rn(f); lo.y = *(unsigned short*)&h;
    h = __float2bfloat16_rn(v.z); f = v.z - __bfloat162float(h); hi.z = *(unsigned short*)&h; h = __float2bfloat16_rn(f); lo.z = *(unsigned short*)&h;
    h = __float2bfloat16_rn(v.w); f = v.w - __bfloat162float(h); hi.w = *(unsigned short*)&h; h = __float2bfloat16_rn(f); lo.w = *(unsigned short*)&h;
    *(ushort4*)((unsigned short*)g_XH + i) = hi;
    *(ushort4*)((unsigned short*)g_XL + i) = lo;
}

__global__ __launch_bounds__(256) void convert_w_kernel(
    const float* __restrict__ Wq, const float* __restrict__ Wk,
    const float* __restrict__ Wv, const float* __restrict__ Wb,
    const float* __restrict__ Wa)
{
    size_t i = ((size_t)blockIdx.x*256 + threadIdx.x)*4;
    int row = (int)(i >> 10);
    int wsel = row >> 10;
    const float* W;
    if      (wsel == 0) W = Wq;
    else if (wsel == 1) W = Wk;
    else if (wsel == 2) W = Wv;
    else if (wsel == 3) W = Wb;
    else                W = Wa;
    size_t li = i - ((size_t)wsel << 20);
    float4 v = *(const float4*)(W + li);
    ushort4 hi, lo;
    float f; __nv_bfloat16 h;
    h = __float2bfloat16_rn(v.x); f = v.x - __bfloat162float(h); hi.x = *(unsigned short*)&h; h = __float2bfloat16_rn(f); lo.x = *(unsigned short*)&h;
    h = __float2bfloat16_rn(v.y); f = v.y - __bfloat162float(h); hi.y = *(unsigned short*)&h; h = __float2bfloat16_rn(f); lo.y = *(unsigned short*)&h;
    h = __float2bfloat16_rn(v.z); f = v.z - __bfloat162float(h); hi.z = *(unsigned short*)&h; h = __float2bfloat16_rn(f); lo.z = *(unsigned short*)&h;
    h = __float2bfloat16_rn(v.w); f = v.w - __bfloat162float(h); hi.w = *(unsigned short*)&h; h = __float2bfloat16_rn(f); lo.w = *(unsigned short*)&h;
    *(ushort4*)((unsigned short*)g_WH + i) = hi;
    *(ushort4*)((unsigned short*)g_WL + i) = lo;
}

// ---------------------------------------------------------------------------
// mma.sync projection GEMM: C[16384 x 5120] = X @ Wcat^T, compensated bf16.
// Block tile 128x128, warp tile 32x64 (4Mx2N warps), K staged 32,
// cp.async double buffer, 80B smem row stride (conflict-free), 2 blocks/SM.
// ---------------------------------------------------------------------------
#define KTILE 32
#define NSTG 32                       /* 1024/32 */
#define PSA_HI 0
#define PSA_LO 10240                  /* 128 rows * 80B */
#define PSB_HI 20480
#define PSB_LO 30720
#define PSTAGE 40960
#define SMEM_PROJ (2*PSTAGE)

__global__ __launch_bounds__(256, 2) void proj_mma_kernel(
    const float* __restrict__ bq, const float* __restrict__ bk,
    const float* __restrict__ bv, const float* __restrict__ bb,
    const float* __restrict__ ba,
    float* __restrict__ out_alpha)
{
    extern __shared__ __align__(16) char smc[];
    const uint32_t sbase = smem_to_u32(smc);

    const int tid  = threadIdx.x;
    const int wid  = tid >> 5;
    const int lane = tid & 31;
    const int wm   = wid & 3;          // 4 warps in M
    const int wn   = wid >> 2;         // 2 warps in N

    const int m0   = blockIdx.x * 128;
    const int n0g  = blockIdx.y * 128;
    const int wsel = blockIdx.y >> 3;
    const int ln0  = (blockIdx.y & 7) * 128;

    const float* bias;
    if      (wsel == 0) bias = bq;
    else if (wsel == 1) bias = bk;
    else if (wsel == 2) bias = bv;
    else if (wsel == 3) bias = bb;
    else                bias = ba;

    float acc[2][8][4];
    #pragma unroll
    for (int i = 0; i < 2; i++)
        #pragma unroll
        for (int j = 0; j < 8; j++)
            #pragma unroll
            for (int c = 0; c < 4; c++) acc[i][j][c] = 0.f;

    // --------- stage loader (cp.async): 4 tiles of 128 rows x 32 bf16 ---------
    auto load_stage = [&](int buf, int k0){
        const uint32_t st = sbase + buf*PSTAGE;
        #pragma unroll
        for (int t = 0; t < 2; t++){
            int i = tid + t*256;             // 0..511 : row = i>>2, 16B chunk = i&3
            int row = i >> 2, c = i & 3;
            uint32_t doff = (uint32_t)(row*80 + c*16);
            CPASYNC(st + PSA_HI + doff, (const char*)(g_XH + (size_t)(m0+row)*DIMV + k0) + c*16);
            CPASYNC(st + PSA_LO + doff, (const char*)(g_XL + (size_t)(m0+row)*DIMV + k0) + c*16);
            CPASYNC(st + PSB_HI + doff, (const char*)(g_WH + (size_t)(n0g+row)*DIMV + k0) + c*16);
            CPASYNC(st + PSB_LO + doff, (const char*)(g_WL + (size_t)(n0g+row)*DIMV + k0) + c*16);
        }
    };

    load_stage(0, 0);
    CP_COMMIT;

    for (int kc = 0; kc < NSTG; kc++){
        if (kc + 1 < NSTG){
            load_stage((kc + 1) & 1, (kc + 1) * KTILE);
            CP_COMMIT;
            CP_WAIT1;
        } else {
            CP_WAIT0;
        }
        __syncthreads();

        const char* sa_hi = smc + (kc & 1)*PSTAGE + PSA_HI;
        const char* sa_lo = smc + (kc & 1)*PSTAGE + PSA_LO;
        const char* sb_hi = smc + (kc & 1)*PSTAGE + PSB_HI;
        const char* sb_lo = smc + (kc & 1)*PSTAGE + PSB_LO;

        #pragma unroll
        for (int ks = 0; ks < 2; ks++){
            const uint32_t c0 = ks*32 + ((lane & 3) << 2);   // byte offset
            uint32_t ah[2][4], al[2][4];
            #pragma unroll
            for (int fm = 0; fm < 2; fm++){
                int r = wm*32 + fm*16 + (lane >> 2);
                ah[fm][0] = *(const uint32_t*)(sa_hi + r*80 + c0);
                ah[fm][1] = *(const uint32_t*)(sa_hi + (r+8)*80 + c0);
                ah[fm][2] = *(const uint32_t*)(sa_hi + r*80 + c0 + 16);
                ah[fm][3] = *(const uint32_t*)(sa_hi + (r+8)*80 + c0 + 16);
                al[fm][0] = *(const uint32_t*)(sa_lo + r*80 + c0);
                al[fm][1] = *(const uint32_t*)(sa_lo + (r+8)*80 + c0);
                al[fm][2] = *(const uint32_t*)(sa_lo + r*80 + c0 + 16);
                al[fm][3] = *(const uint32_t*)(sa_lo + (r+8)*80 + c0 + 16);
            }
            #pragma unroll
            for (int fn = 0; fn < 8; fn++){
                int n = wn*64 + fn*8 + (lane >> 2);
                uint32_t bh0 = *(const uint32_t*)(sb_hi + n*80 + c0);
                uint32_t bh1 = *(const uint32_t*)(sb_hi + n*80 + c0 + 16);
                uint32_t bl0 = *(const uint32_t*)(sb_lo + n*80 + c0);
                uint32_t bl1 = *(const uint32_t*)(sb_lo + n*80 + c0 + 16);
                #pragma unroll
                for (int fm = 0; fm < 2; fm++){
                    MMA_BF16(acc[fm][fn], ah[fm][0], ah[fm][1], ah[fm][2], ah[fm][3], bh0, bh1);
                    MMA_BF16(acc[fm][fn], ah[fm][0], ah[fm][1], ah[fm][2], ah[fm][3], bl0, bl1);
                    MMA_BF16(acc[fm][fn], al[fm][0], al[fm][1], al[fm][2], al[fm][3], bh0, bh1);
                }
            }
        }
        __syncthreads();
    }

    // --------- epilogue: bias + activation, direct 8B stores ---------
    const float scale = 0.125f;
    #pragma unroll
    for (int fm = 0; fm < 2; fm++){
        int r0 = m0 + wm*32 + fm*16 + (lane >> 2);
        #pragma unroll
        for (int fn = 0; fn < 8; fn++){
            int ln = ln0 + wn*64 + fn*8 + ((lane & 3) << 1);
            float b0 = bias[ln], b1 = bias[ln+1];
            #pragma unroll
            for (int half = 0; half < 2; half++){
                int r = r0 + half*8;
                float v0 = acc[fm][fn][half*2 + 0] + b0;
                float v1 = acc[fm][fn][half*2 + 1] + b1;
                size_t oidx = (size_t)r*DIMV + ln;
                if (wsel == 0){
                    float2 o = {v0*scale, v1*scale};
                    *(float2*)&g_Q[oidx] = o;
                } else if (wsel == 1){
                    float2 o = {v0*scale, v1*scale};
                    *(float2*)&g_K[oidx] = o;
                } else if (wsel == 2){
                    float2 o = {v0, v1};
                    *(float2*)&g_V[oidx] = o;
                } else if (wsel == 3){
                    float2 o = {softplusf(v0), softplusf(v1)};
                    *(float2*)&g_BETA[oidx] = o;
                } else {
                    float z0 = fminf(fmaxf(v0,-10.f),10.f);
                    float z1 = fminf(fmaxf(v1,-10.f),10.f);
                    float2 oa = {1.f/(1.f+expf(-z0)), 1.f/(1.f+expf(-z1))};
                    *(float2*)&out_alpha[oidx] = oa;
                    float2 ol = {fminf(z0,0.f) - log1pf(expf(-fabsf(z0))),
                                 fminf(z1,0.f) - log1pf(expf(-fabsf(z1)))};
                    *(float2*)&g_LA[oidx] = ol;
                }
            }
        }
    }
}

// ---------------------------------------------------------------------------
// Kernel 2: per-(b,n,h) chunk stats
// ---------------------------------------------------------------------------
__global__ __launch_bounds__(128) void mstat_kernel()
{
    const int h = blockIdx.x & 15;
    const int n = (blockIdx.x >> 4) & 31;
    const int b = blockIdx.x >> 9;
    const int c = threadIdx.x;
    size_t base = ((size_t)(b*TLEN + n*CHK + c))*DIMV + h*HDIM;
    float sla = 0.f, sbe = 0.f;
    #pragma unroll
    for (int q = 0; q < 16; q++){
        float4 la4 = *(const float4*)&g_LA[base + q*4];
        float4 be4 = *(const float4*)&g_BETA[base + q*4];
        sla += la4.x + la4.y + la4.z + la4.w;
        sbe += be4.x + be4.y + be4.z + be4.w;
    }
    sla *= (1.f/64.f);
    sbe *= (1.f/64.f);

    __shared__ float sbuf[128];
    sbuf[c] = sla;
    __syncthreads();
    for (int off = 1; off < 128; off <<= 1){
        float t = (c >= off) ? sbuf[c - off] : 0.f;
        __syncthreads();
        sbuf[c] += t;
        __syncthreads();
    }
    int oidx = ((b*NCH + n)*NH + h)*CHK + c;
    g_M[oidx]  = sbuf[c];
    g_BM[oidx] = sbe;
}

// ---------------------------------------------------------------------------
// Kernel 3: sequential state scan, one block per (b,h)
// ---------------------------------------------------------------------------
#define SCAN_FLOATS (64*68 + 128*64 + 128*64 + 128)
#define SCAN_SMEM   (SCAN_FLOATS*4)

__global__ __launch_bounds__(256) void scan_state_kernel(float* __restrict__ state_out)
{
    extern __shared__ __align__(16) float smcx[];
    float* St = smcx;
    float* Ks = St + 64*68;
    float* Vs = Ks + 128*64;
    float* bm = Vs + 128*64;

    const int b = blockIdx.x >> 4;
    const int h = blockIdx.x & 15;
    const int tid = threadIdx.x;
    const int tx = tid & 15, ty = tid >> 4;

    for (int i = tid; i < 64*68; i += 256) St[i] = 0.f;
    __syncthreads();

    for (int n = 0; n < NCH; n++){
        size_t snbase = ((((size_t)b*NH + h)*NCH + n)) << 12;
        for (int i = tid; i < 4096; i += 256)
            g_SN[snbase + i] = St[(i >> 6)*68 + (i & 63)];
        #pragma unroll
        for (int kq = 0; kq < 8; kq++){
            int id  = tid + kq*256;
            int row = id >> 4, c4 = id & 15;
            size_t ga = ((size_t)(b*TLEN + n*CHK + row))*DIMV + h*HDIM + c4*4;
            *(float4*)&Ks[row*64 + c4*4] = *(const float4*)&g_K[ga];
            *(float4*)&Vs[row*64 + c4*4] = *(const float4*)&g_V[ga];
        }
        if (tid < 128) bm[tid] = g_BM[((b*NCH + n)*NH + h)*CHK + tid];
        __syncthreads();

        float d[4][4];
        #pragma unroll
        for (int r = 0; r < 4; r++)
            #pragma unroll
            for (int cv = 0; cv < 4; cv++) d[r][cv] = 0.f;

        for (int cc = 0; cc < CHK; cc++){
            float bmv = bm[cc];
            float4 v4 = *(float4*)&Vs[cc*64 + tx*4];
            v4.x *= bmv; v4.y *= bmv; v4.z *= bmv; v4.w *= bmv;
            #pragma unroll
            for (int r = 0; r < 4; r++){
                float kv = Ks[cc*64 + ty*4 + r];
                d[r][0] += kv*v4.x; d[r][1] += kv*v4.y;
                d[r][2] += kv*v4.z; d[r][3] += kv*v4.w;
            }
        }
        float asum = __expf(g_M[((b*NCH + n)*NH + h)*CHK + 127]);
        #pragma unroll
        for (int r = 0; r < 4; r++)
            #pragma unroll
            for (int cv = 0; cv < 4; cv++){
                int idx = (ty*4 + r)*68 + tx*4 + cv;
                St[idx] = St[idx]*asum + d[r][cv];
            }
        __syncthreads();
    }
    size_t ob = ((size_t)(b*NH + h)) << 12;
    for (int i = tid; i < 4096; i += 256)
        state_out[ob + i] = St[(i >> 6)*68 + (i & 63)];
}

// ---------------------------------------------------------------------------
// Kernel 4: fused intra-chunk attention + inter-chunk memory readout
// ---------------------------------------------------------------------------
#define INTRA_FLOATS (64*132 + 64*132 + 128*132 + 128*64 + 64*68 + 128)
#define INTRA_SMEM   (INTRA_FLOATS*4)

__global__ __launch_bounds__(256) void intra_kernel(float* __restrict__ y_out)
{
    extern __shared__ __align__(16) float smi[];
    float* QT   = smi;
    float* KTs  = QT + 64*132;
    float* Ssm  = KTs + 64*132;
    float* VB   = Ssm + 128*132;
    float* SN   = VB + 128*64;
    float* msh  = SN + 64*68;

    const int h = blockIdx.x & 15;
    const int n = (blockIdx.x >> 4) & 31;
    const int b = blockIdx.x >> 9;
    const int tid = threadIdx.x;
    const int tx = tid & 15, ty = tid >> 4;

    #pragma unroll
    for (int kq = 0; kq < 8; kq++){
        int id  = tid + kq*256;
        int row = id >> 4, c4 = id & 15;
        size_t ga = ((size_t)(b*TLEN + n*CHK + row))*DIMV + h*HDIM + c4*4;
        float4 q4  = *(const float4*)&g_Q[ga];
        float4 k4  = *(const float4*)&g_K[ga];
        float4 v4  = *(const float4*)&g_V[ga];
        float4 be4 = *(const float4*)&g_BETA[ga];
        int dd = c4*4;
        QT[(dd+0)*132+row]=q4.x; QT[(dd+1)*132+row]=q4.y;
        QT[(dd+2)*132+row]=q4.z; QT[(dd+3)*132+row]=q4.w;
        KTs[(dd+0)*132+row]=k4.x; KTs[(dd+1)*132+row]=k4.y;
        KTs[(dd+2)*132+row]=k4.z; KTs[(dd+3)*132+row]=k4.w;
        float4 vb4;
        vb4.x = v4.x*be4.x; vb4.y = v4.y*be4.y;
        vb4.z = v4.z*be4.z; vb4.w = v4.w*be4.w;
        *(float4*)&VB[row*64 + dd] = vb4;
    }
    {
        size_t snbase = ((((size_t)b*NH + h)*NCH + n)) << 12;
        for (int i = tid; i < 4096; i += 256)
            SN[(i >> 6)*68 + (i & 63)] = g_SN[snbase + i];
        if (tid < 128) msh[tid] = g_M[((b*NCH + n)*NH + h)*CHK + tid];
    }
    __syncthreads();

    float acc1[8][8];
    #pragma unroll
    for (int i = 0; i < 8; i++)
        #pragma unroll
        for (int j = 0; j < 8; j++) acc1[i][j] = 0.f;

    for (int dd = 0; dd < 64; dd++){
        float4 a0 = *(float4*)&QT[dd*132 + ty*4];
        float4 a1 = *(float4*)&QT[dd*132 + 64 + ty*4];
        float4 b0 = *(float4*)&KTs[dd*132 + tx*4];
        float4 b1 = *(float4*)&KTs[dd*132 + 64 + tx*4];
        float a[8]  = {a0.x,a0.y,a0.z,a0.w, a1.x,a1.y,a1.z,a1.w};
        float bb8[8]= {b0.x,b0.y,b0.z,b0.w, b1.x,b1.y,b1.z,b1.w};
        #pragma unroll
        for (int i = 0; i < 8; i++)
            #pragma unroll
            for (int j = 0; j < 8; j++) acc1[i][j] += a[i]*bb8[j];
    }

    #pragma unroll
    for (int i = 0; i < 8; i++){
        int ig = (i < 4) ? ty*4+i : 64 + ty*4 + (i-4);
        float mi = msh[ig];
        #pragma unroll
        for (int j = 0; j < 8; j++){
            int jg = (j < 4) ? tx*4+j : 64 + tx*4 + (j-4);
            float s = (jg <= ig) ? acc1[i][j]*__expf(mi - msh[jg]) : 0.f;
            Ssm[ig*132 + jg] = s;
        }
    }
    __syncthreads();

    float accY[8][4], accM[8][4];
    #pragma unroll
    for (int i = 0; i < 8; i++)
        #pragma unroll
        for (int c = 0; c < 4; c++){ accY[i][c] = 0.f; accM[i][c] = 0.f; }

    for (int j = 0; j < 128; j++){
        float4 vb4 = *(float4*)&VB[j*64 + tx*4];
        #pragma unroll
        for (int i = 0; i < 8; i++){
            int ig = (i < 4) ? ty*4+i : 64 + ty*4 + (i-4);
            float s = Ssm[ig*132 + j];
            accY[i][0] += s*vb4.x; accY[i][1] += s*vb4.y;
            accY[i][2] += s*vb4.z; accY[i][3] += s*vb4.w;
        }
    }
    for (int q = 0; q < 64; q++){
        float4 s4 = *(float4*)&SN[q*68 + tx*4];
        #pragma unroll
        for (int i = 0; i < 8; i++){
            int ig = (i < 4) ? ty*4+i : 64 + ty*4 + (i-4);
            float qv = QT[q*132 + ig];
            accM[i][0] += qv*s4.x; accM[i][1] += qv*s4.y;
            accM[i][2] += qv*s4.z; accM[i][3] += qv*s4.w;
        }
    }

    #pragma unroll
    for (int i = 0; i < 8; i++){
        int ig = (i < 4) ? ty*4+i : 64 + ty*4 + (i-4);
        float cv = __expf(msh[ig]);
        float4 o;
        o.x = accY[i][0] + cv*accM[i][0];
        o.y = accY[i][1] + cv*accM[i][1];
        o.z = accY[i][2] + cv*accM[i][2];
        o.w = accY[i][3] + cv*accM[i][3];
        size_t oa = ((size_t)(b*TLEN + n*CHK + ig))*DIMV + h*HDIM + tx*4;
        *(float4*)&y_out[oa] = o;
    }
}

// ---------------------------------------------------------------------------
extern "C" void kernel_launch(void* const* d_in, const int* in_sizes, int n_in,
                              void* d_out, int out_size)
{
    const float* x  = (const float*)d_in[0];
    const float* Wq = (const float*)d_in[1];
    const float* bq = (const float*)d_in[2];
    const float* Wk = (const float*)d_in[3];
    const float* bk = (const float*)d_in[4];
    const float* Wv = (const float*)d_in[5];
    const float* bv = (const float*)d_in[6];
    const float* Wb = (const float*)d_in[7];
    const float* bb = (const float*)d_in[8];
    const float* Wa = (const float*)d_in[9];
    const float* ba = (const float*)d_in[10];

    float* out       = (float*)d_out;
    float* y_out     = out;
    float* state_out = out + Y_ELEMS;
    float* alpha_out = out + Y_ELEMS + ST_ELEMS;

    cudaFuncSetAttribute(proj_mma_kernel,
                         cudaFuncAttributeMaxDynamicSharedMemorySize, SMEM_PROJ);
    cudaFuncSetAttribute(scan_state_kernel,
                         cudaFuncAttributeMaxDynamicSharedMemorySize, SCAN_SMEM);
    cudaFuncSetAttribute(intra_kernel,
                         cudaFuncAttributeMaxDynamicSharedMemorySize, INTRA_SMEM);

    convert_x_kernel<<<MROWS*DIMV/4/256, 256>>>(x);
    convert_w_kernel<<<NTOT*DIMV/4/256, 256>>>(Wq, Wk, Wv, Wb, Wa);

    dim3 gp(128, 40);
    proj_mma_kernel<<<gp, 256, SMEM_PROJ>>>(bq, bk, bv, bb, ba, alpha_out);

    mstat_kernel<<<BSZ*NCH*NH, 128>>>();
    scan_state_kernel<<<BSZ*NH, 256, SCAN_SMEM>>>(state_out);
    intra_kernel<<<BSZ*NCH*NH, 256, INTRA_SMEM>>>(y_out);
}